// round 7
// baseline (speedup 1.0000x reference)
#include <cuda_runtime.h>
#include <cstdint>

#define EDIM    8
#define NCODES  1024
#define NPAIR   512          // NCODES/2
#define SP      32768        // 32*32*32 spatial per batch
#define THREADS 128
#define QPT     2            // queries per thread

typedef unsigned long long ull;

// ---- constant-memory codebook (uniform-port loads in the hot loop) ----
// cE2[p*4+k] = { pack2(e[2p][2k], e[2p+1][2k]), pack2(e[2p][2k+1], e[2p+1][2k+1]) }
// cEE[p]     = pack2(||e[2p]||^2, ||e[2p+1]||^2)
__constant__ ulonglong2 cE2[NPAIR * 4];   // 32 KB
__constant__ ull        cEE[NPAIR];       //  4 KB

// ---- device scratch (no allocations; self-resetting across graph replays) ----
__device__ ulonglong2 g_stageA[NPAIR * 4];
__device__ ull        g_stageB[NPAIR];
__device__ float      g_partial[4096];
__device__ int        g_used[NCODES];
__device__ unsigned   g_ticket = 0;

// ---- packed f32x2 helpers (Blackwell FFMA2 path, PTX-only) ----
__device__ __forceinline__ ull pack2(float lo, float hi){
    ull d;
    asm("mov.b64 %0, {%1, %2};" : "=l"(d)
        : "r"(__float_as_uint(lo)), "r"(__float_as_uint(hi)));
    return d;
}
__device__ __forceinline__ ull fma2(ull a, ull b, ull c){
    ull d; asm("fma.rn.f32x2 %0, %1, %2, %3;" : "=l"(d) : "l"(a), "l"(b), "l"(c));
    return d;
}
__device__ __forceinline__ ull mul2(ull a, ull b){
    ull d; asm("mul.rn.f32x2 %0, %1, %2;" : "=l"(d) : "l"(a), "l"(b));
    return d;
}
__device__ __forceinline__ ull add2(ull a, ull b){
    ull d; asm("add.rn.f32x2 %0, %1, %2;" : "=l"(d) : "l"(a), "l"(b));
    return d;
}
union U64F2 { ull u; float2 f; };
__device__ __forceinline__ float2 asf2(ull v){ U64F2 x; x.u = v; return x.f; }

// Bit-exact pair distance: d_pair = fma2(dot2, {-2,-2}, add2(ee2, zz2))
// (this exact op structure reproduces the reference's rounding; do not change)
__device__ __forceinline__ ull pair_dist_v(ulonglong2 e01, ulonglong2 e23,
                                           ulonglong2 e45, ulonglong2 e67,
                                           ull eep, const ull* zp, ull zzp, ull m2){
    ull a = mul2(zp[0], e01.x);
    a = fma2(zp[1], e01.y, a);
    a = fma2(zp[2], e23.x, a);
    a = fma2(zp[3], e23.y, a);
    a = fma2(zp[4], e45.x, a);
    a = fma2(zp[5], e45.y, a);
    a = fma2(zp[6], e67.x, a);
    a = fma2(zp[7], e67.y, a);
    return fma2(a, m2, add2(eep, zzp));
}

// ---- repack emb into staging (then D2D memcpy to __constant__) ----
__global__ void vq_repack(const float* __restrict__ emb){
    const int p = blockIdx.x * blockDim.x + threadIdx.x;
    if (p < NPAIR){
        float e0[EDIM], e1[EDIM];
        float s0 = 0.f, s1 = 0.f;
        #pragma unroll
        for (int c = 0; c < EDIM; c++){
            e0[c] = emb[(2*p)*EDIM + c];
            e1[c] = emb[(2*p+1)*EDIM + c];
            s0 = fmaf(e0[c], e0[c], s0);
            s1 = fmaf(e1[c], e1[c], s1);
        }
        #pragma unroll
        for (int k = 0; k < 4; k++){
            ulonglong2 v;
            v.x = pack2(e0[2*k],   e1[2*k]);
            v.y = pack2(e0[2*k+1], e1[2*k+1]);
            g_stageA[p*4 + k] = v;
        }
        g_stageB[p] = pack2(s0, s1);
    }
}

// ---- fused search + epilogue + ticket-gated finalize ----
__global__ __launch_bounds__(THREADS, 7) void vq_main(
    const float* __restrict__ z,
    float* __restrict__ out,
    int Nvec, int nblocks)
{
    __shared__ float sRed[THREADS / 32];
    __shared__ bool  sLast;

    const int part = Nvec >> 1;                 // Nvec / QPT
    const int t = blockIdx.x * THREADS + threadIdx.x;
    float lossLocal = 0.f;

    if (t < part) {
        int nq[QPT], bq[QPT], sq[QPT];
        ull zp[QPT][EDIM];
        ull zzp[QPT];

        #pragma unroll
        for (int q = 0; q < QPT; q++){
            nq[q] = t + q * part;
            bq[q] = nq[q] >> 15;
            sq[q] = nq[q] & (SP - 1);
            const float* zptr = z + (size_t)bq[q] * (EDIM * SP) + sq[q];
            float zz = 0.f;
            #pragma unroll
            for (int c = 0; c < EDIM; c++){
                float v = zptr[c * SP];
                zp[q][c] = pack2(v, v);
                zz = fmaf(v, v, zz);
            }
            zzp[q] = pack2(zz, zz);
        }
        const ull m2 = pack2(-2.f, -2.f);

        float best[QPT];
        int   bip[QPT];                         // winning PAIR index
        #pragma unroll
        for (int q = 0; q < QPT; q++){ best[q] = 3.4e38f; bip[q] = 0; }

        // Two pairs per iteration; codebook comes from __constant__ with a
        // warp-uniform index -> uniform-port LDCU, zero LDS crossbar traffic.
        #pragma unroll 2
        for (int p = 0; p < NPAIR; p += 2){
            const ulonglong2 a01 = cE2[p*4+0], a23 = cE2[p*4+1];
            const ulonglong2 a45 = cE2[p*4+2], a67 = cE2[p*4+3];
            const ull eepA = cEE[p];
            const ulonglong2 b01 = cE2[p*4+4], b23 = cE2[p*4+5];
            const ulonglong2 b45 = cE2[p*4+6], b67 = cE2[p*4+7];
            const ull eepB = cEE[p+1];

            float2 dA0 = asf2(pair_dist_v(a01,a23,a45,a67, eepA, zp[0], zzp[0], m2));
            float2 dB0 = asf2(pair_dist_v(b01,b23,b45,b67, eepB, zp[0], zzp[0], m2));
            float2 dA1 = asf2(pair_dist_v(a01,a23,a45,a67, eepA, zp[1], zzp[1], m2));
            float2 dB1 = asf2(pair_dist_v(b01,b23,b45,b67, eepB, zp[1], zzp[1], m2));

            // sequential compares preserve first-occurrence argmin
            {
                float dm = fminf(dA0.x, dA0.y);
                bool u = dm < best[0]; bip[0] = u ? p : bip[0]; best[0] = fminf(best[0], dm);
                dm = fminf(dB0.x, dB0.y);
                u = dm < best[0]; bip[0] = u ? (p + 1) : bip[0]; best[0] = fminf(best[0], dm);
            }
            {
                float dm = fminf(dA1.x, dA1.y);
                bool u = dm < best[1]; bip[1] = u ? p : bip[1]; best[1] = fminf(best[1], dm);
                dm = fminf(dB1.x, dB1.y);
                u = dm < best[1]; bip[1] = u ? (p + 1) : bip[1]; best[1] = fminf(best[1], dm);
            }
        }

        // Epilogue: resolve even/odd half (bit-exact recompute), gather, loss, idx
        const int n_z = Nvec * EDIM;
        #pragma unroll
        for (int q = 0; q < QPT; q++){
            const int p = bip[q];
            const ulonglong2 e01 = cE2[p*4+0], e23 = cE2[p*4+1];
            const ulonglong2 e45 = cE2[p*4+2], e67 = cE2[p*4+3];
            const ull eep = cEE[p];
            float2 df = asf2(pair_dist_v(e01,e23,e45,e67, eep, zp[q], zzp[q], m2));
            const int sel = (df.y < df.x) ? 1 : 0;   // tie -> even (first index)
            const int bi = 2 * p + sel;

            float* o = out + (size_t)bq[q] * (EDIM * SP) + sq[q];
            ull ecode[EDIM/2 ? 4 : 4];
            ecode[0] = e01.x; ecode[1] = e01.y;
            ull etmp[8] = { e01.x, e01.y, e23.x, e23.y, e45.x, e45.y, e67.x, e67.y };
            #pragma unroll
            for (int c = 0; c < EDIM; c++){
                float2 ev = asf2(etmp[c]);
                float e = sel ? ev.y : ev.x;
                o[c * SP] = e;
                float zc = asf2(zp[q][c]).x;
                float dfc = e - zc;
                lossLocal = fmaf(dfc, dfc, lossLocal);
            }
            out[n_z + 2 + nq[q]] = (float)bi;
            g_used[bi] = 1;
        }
    }

    // Block-reduce loss -> deterministic per-block partial
    #pragma unroll
    for (int o = 16; o > 0; o >>= 1)
        lossLocal += __shfl_down_sync(0xffffffff, lossLocal, o);
    const int lane = threadIdx.x & 31, w = threadIdx.x >> 5;
    if (lane == 0) sRed[w] = lossLocal;
    __syncthreads();
    if (threadIdx.x == 0){
        float v = 0.f;
        #pragma unroll
        for (int i = 0; i < THREADS / 32; i++) v += sRed[i];
        g_partial[blockIdx.x] = v;
        __threadfence();
        unsigned old = atomicAdd(&g_ticket, 1u);
        sLast = (old == (unsigned)(nblocks - 1));
    }
    __syncthreads();

    // Last block to finish performs finalization (deterministic result)
    if (sLast){
        __threadfence();
        const int n_z = Nvec * EDIM;

        int cnt = 0;
        for (int i = threadIdx.x; i < NCODES; i += THREADS){
            cnt += (g_used[i] != 0);
            g_used[i] = 0;                      // reset for next replay
        }
        float s = 0.f;
        for (int i = threadIdx.x; i < nblocks; i += THREADS) s += g_partial[i];

        #pragma unroll
        for (int o = 16; o > 0; o >>= 1){
            s   += __shfl_down_sync(0xffffffff, s, o);
            cnt += __shfl_down_sync(0xffffffff, cnt, o);
        }
        __shared__ float rs[THREADS / 32];
        __shared__ int   rc[THREADS / 32];
        if (lane == 0){ rs[w] = s; rc[w] = cnt; }
        __syncthreads();
        if (threadIdx.x == 0){
            float total = 0.f; int ctotal = 0;
            #pragma unroll
            for (int i = 0; i < THREADS / 32; i++){ total += rs[i]; ctotal += rc[i]; }
            // loss = beta*mean + mean = 1.25 * sum((z_q - z)^2) / n_z
            out[n_z]     = 1.25f * total / (float)n_z;
            out[n_z + 1] = (float)ctotal;
            __threadfence();
            g_ticket = 0;                       // reset for next graph replay
        }
    }
}

extern "C" void kernel_launch(void* const* d_in, const int* in_sizes, int n_in,
                              void* d_out, int out_size)
{
    const float* z   = (const float*)d_in[0];
    const float* emb = (const float*)d_in[1];
    float* out = (float*)d_out;

    const int n_z  = in_sizes[0];      // 2,097,152
    const int Nvec = n_z / EDIM;       // 262,144

    // 1) repack codebook into staging, 2) D2D copy into __constant__
    vq_repack<<<(NPAIR + 127) / 128, 128>>>(emb);
    void* pA = nullptr; void* pB = nullptr;
    cudaGetSymbolAddress(&pA, g_stageA);
    cudaGetSymbolAddress(&pB, g_stageB);
    cudaMemcpyToSymbolAsync(cE2, pA, sizeof(ulonglong2) * NPAIR * 4, 0,
                            cudaMemcpyDeviceToDevice, 0);
    cudaMemcpyToSymbolAsync(cEE, pB, sizeof(ull) * NPAIR, 0,
                            cudaMemcpyDeviceToDevice, 0);

    const int part = Nvec / QPT;
    const int nblocks = (part + THREADS - 1) / THREADS;   // 1024
    vq_main<<<nblocks, THREADS>>>(z, out, Nvec, nblocks);
}

// round 8
// speedup vs baseline: 1.6757x; 1.6757x over previous
#include <cuda_runtime.h>
#include <cstdint>

#define EDIM    8
#define NCODES  1024
#define NPAIR   512          // NCODES/2
#define SP      32768        // 32*32*32 spatial per batch
#define THREADS 128
#define QPT     2            // queries per thread

typedef unsigned long long ull;

// ---- device scratch (no allocations; self-resetting across graph replays) ----
__device__ float    g_partial[4096];   // per-block loss partials (overwritten each run)
__device__ int      g_used[NCODES];    // set by main, counted+reset by finalizer
__device__ unsigned g_ticket = 0;      // completion ticket; finalizer resets to 0

// ---- packed f32x2 helpers (Blackwell FFMA2 path, PTX-only) ----
__device__ __forceinline__ ull pack2(float lo, float hi){
    ull d;
    asm("mov.b64 %0, {%1, %2};" : "=l"(d)
        : "r"(__float_as_uint(lo)), "r"(__float_as_uint(hi)));
    return d;
}
__device__ __forceinline__ ull fma2(ull a, ull b, ull c){
    ull d; asm("fma.rn.f32x2 %0, %1, %2, %3;" : "=l"(d) : "l"(a), "l"(b), "l"(c));
    return d;
}
__device__ __forceinline__ ull mul2(ull a, ull b){
    ull d; asm("mul.rn.f32x2 %0, %1, %2;" : "=l"(d) : "l"(a), "l"(b));
    return d;
}
__device__ __forceinline__ ull add2(ull a, ull b){
    ull d; asm("add.rn.f32x2 %0, %1, %2;" : "=l"(d) : "l"(a), "l"(b));
    return d;
}
union U64F2 { ull u; float2 f; };
__device__ __forceinline__ float2 asf2(ull v){ U64F2 x; x.u = v; return x.f; }

// Bit-exact pair distance: d_pair = fma2(dot2, {-2,-2}, add2(ee2, zz2))
// (this exact op structure reproduces the reference's rounding; do not change)
__device__ __forceinline__ ull pair_dist(const ulonglong2* ep, ull eep,
                                         const ull* zp, ull zzp, ull m2){
    const ulonglong2 e01 = ep[0];
    const ulonglong2 e23 = ep[1];
    const ulonglong2 e45 = ep[2];
    const ulonglong2 e67 = ep[3];
    ull a = mul2(zp[0], e01.x);
    a = fma2(zp[1], e01.y, a);
    a = fma2(zp[2], e23.x, a);
    a = fma2(zp[3], e23.y, a);
    a = fma2(zp[4], e45.x, a);
    a = fma2(zp[5], e45.y, a);
    a = fma2(zp[6], e67.x, a);
    a = fma2(zp[7], e67.y, a);
    return fma2(a, m2, add2(eep, zzp));
}

// ---- single fused kernel: search + epilogue + ticket-gated finalize ----
__global__ __launch_bounds__(THREADS, 7) void vq_main(
    const float* __restrict__ z,
    const float* __restrict__ emb,
    float* __restrict__ out,
    int Nvec, int nblocks)
{
    __shared__ __align__(16) float2 sE[NPAIR * EDIM];  // pair-packed codebook, 32KB
    __shared__ __align__(16) float  sEE[NCODES];       // ||e||^2, 4KB
    __shared__ float sRed[THREADS / 32];
    __shared__ bool  sLast;

    // Stage codebook: sE[p*8+c] = (e[2p][c], e[2p+1][c])
    for (int i = threadIdx.x; i < NPAIR * EDIM; i += THREADS){
        int p = i >> 3, c = i & 7;
        sE[i] = make_float2(emb[(2*p)*EDIM + c], emb[(2*p+1)*EDIM + c]);
    }
    for (int j = threadIdx.x; j < NCODES; j += THREADS){
        float s = 0.f;
        #pragma unroll
        for (int c = 0; c < EDIM; c++){ float e = emb[j*EDIM + c]; s = fmaf(e, e, s); }
        sEE[j] = s;
    }
    __syncthreads();

    const int part = Nvec >> 1;                 // Nvec / QPT
    const int t = blockIdx.x * THREADS + threadIdx.x;
    float lossLocal = 0.f;

    if (t < part) {
        int nq[QPT], bq[QPT], sq[QPT];
        ull zp[QPT][EDIM];
        ull zzp[QPT];

        #pragma unroll
        for (int q = 0; q < QPT; q++){
            nq[q] = t + q * part;
            bq[q] = nq[q] >> 15;
            sq[q] = nq[q] & (SP - 1);
            const float* zptr = z + (size_t)bq[q] * (EDIM * SP) + sq[q];
            float zz = 0.f;
            #pragma unroll
            for (int c = 0; c < EDIM; c++){
                float v = zptr[c * SP];
                zp[q][c] = pack2(v, v);
                zz = fmaf(v, v, zz);
            }
            zzp[q] = pack2(zz, zz);
        }
        const ull m2 = pack2(-2.f, -2.f);

        float best[QPT];
        int   bgp[QPT];                         // winning GROUP base pair (even)
        #pragma unroll
        for (int q = 0; q < QPT; q++){ best[q] = 3.4e38f; bgp[q] = 0; }

        // Group of 2 pairs per step; one compare/update per group per query.
        // Norms for both pairs fetched with a single 16B LDS (p even -> aligned).
        #pragma unroll 2
        for (int p = 0; p < NPAIR; p += 2){
            const ulonglong2* epA = reinterpret_cast<const ulonglong2*>(sE + p * EDIM);
            const ulonglong2* epB = reinterpret_cast<const ulonglong2*>(sE + (p + 1) * EDIM);
            const ulonglong2 eeAB = *reinterpret_cast<const ulonglong2*>(sEE + 2 * p);

            float2 dA0 = asf2(pair_dist(epA, eeAB.x, zp[0], zzp[0], m2));
            float2 dB0 = asf2(pair_dist(epB, eeAB.y, zp[0], zzp[0], m2));
            float2 dA1 = asf2(pair_dist(epA, eeAB.x, zp[1], zzp[1], m2));
            float2 dB1 = asf2(pair_dist(epB, eeAB.y, zp[1], zzp[1], m2));

            {
                float gm = fminf(fminf(dA0.x, dA0.y), fminf(dB0.x, dB0.y));
                bool u = gm < best[0];          // strict: earliest group wins ties
                bgp[0] = u ? p : bgp[0];
                best[0] = fminf(best[0], gm);
            }
            {
                float gm = fminf(fminf(dA1.x, dA1.y), fminf(dB1.x, dB1.y));
                bool u = gm < best[1];
                bgp[1] = u ? p : bgp[1];
                best[1] = fminf(best[1], gm);
            }
        }

        // Epilogue: rescan winning 2-pair group (bit-exact), first-occurrence argmin
        const int n_z = Nvec * EDIM;
        #pragma unroll
        for (int q = 0; q < QPT; q++){
            const int gp = bgp[q];
            float bd = 3.4e38f;
            int bi = 0, bp = 0, bsel = 0;
            #pragma unroll
            for (int j = 0; j < 2; j++){
                const int p = gp + j;
                const ulonglong2* ep = reinterpret_cast<const ulonglong2*>(sE + p * EDIM);
                const ull eep = *reinterpret_cast<const ull*>(sEE + 2 * p);
                float2 df = asf2(pair_dist(ep, eep, zp[q], zzp[q], m2));
                if (df.x < bd){ bd = df.x; bi = 2*p;     bp = p; bsel = 0; }
                if (df.y < bd){ bd = df.y; bi = 2*p + 1; bp = p; bsel = 1; }
            }

            float* o = out + (size_t)bq[q] * (EDIM * SP) + sq[q];
            #pragma unroll
            for (int c = 0; c < EDIM; c++){
                float2 ev = sE[bp * EDIM + c];
                float e = bsel ? ev.y : ev.x;
                o[c * SP] = e;
                float zc = asf2(zp[q][c]).x;
                float dfc = e - zc;
                lossLocal = fmaf(dfc, dfc, lossLocal);
            }
            out[n_z + 2 + nq[q]] = (float)bi;
            g_used[bi] = 1;
        }
    }

    // Block-reduce loss -> deterministic per-block partial
    #pragma unroll
    for (int o = 16; o > 0; o >>= 1)
        lossLocal += __shfl_down_sync(0xffffffff, lossLocal, o);
    const int lane = threadIdx.x & 31, w = threadIdx.x >> 5;
    if (lane == 0) sRed[w] = lossLocal;
    __syncthreads();
    if (threadIdx.x == 0){
        float v = 0.f;
        #pragma unroll
        for (int i = 0; i < THREADS / 32; i++) v += sRed[i];
        g_partial[blockIdx.x] = v;
        __threadfence();
        unsigned old = atomicAdd(&g_ticket, 1u);
        sLast = (old == (unsigned)(nblocks - 1));
    }
    __syncthreads();

    // Last block to finish performs finalization (deterministic result)
    if (sLast){
        __threadfence();
        const int n_z = Nvec * EDIM;

        int cnt = 0;
        for (int i = threadIdx.x; i < NCODES; i += THREADS){
            cnt += (g_used[i] != 0);
            g_used[i] = 0;                      // reset for next replay
        }
        float s = 0.f;
        for (int i = threadIdx.x; i < nblocks; i += THREADS) s += g_partial[i];

        #pragma unroll
        for (int o = 16; o > 0; o >>= 1){
            s   += __shfl_down_sync(0xffffffff, s, o);
            cnt += __shfl_down_sync(0xffffffff, cnt, o);
        }
        __shared__ float rs[THREADS / 32];
        __shared__ int   rc[THREADS / 32];
        if (lane == 0){ rs[w] = s; rc[w] = cnt; }
        __syncthreads();
        if (threadIdx.x == 0){
            float total = 0.f; int ctotal = 0;
            #pragma unroll
            for (int i = 0; i < THREADS / 32; i++){ total += rs[i]; ctotal += rc[i]; }
            // loss = beta*mean + mean = 1.25 * sum((z_q - z)^2) / n_z
            out[n_z]     = 1.25f * total / (float)n_z;
            out[n_z + 1] = (float)ctotal;
            __threadfence();
            g_ticket = 0;                       // reset for next graph replay
        }
    }
}

extern "C" void kernel_launch(void* const* d_in, const int* in_sizes, int n_in,
                              void* d_out, int out_size)
{
    const float* z   = (const float*)d_in[0];
    const float* emb = (const float*)d_in[1];
    float* out = (float*)d_out;

    const int n_z  = in_sizes[0];      // 2,097,152
    const int Nvec = n_z / EDIM;       // 262,144

    const int part = Nvec / QPT;
    const int nblocks = (part + THREADS - 1) / THREADS;   // 1024
    vq_main<<<nblocks, THREADS>>>(z, emb, out, Nvec, nblocks);
}